// round 7
// baseline (speedup 1.0000x reference)
#include <cuda_runtime.h>
#include <cuda_bf16.h>
#include <mma.h>
#include <type_traits>

using namespace nvcuda;

#define SEQ  2048
#define HID  2048
#define AKEY 1024

// ---------------------------------------------------------------------------
// Scratch (device-global; no runtime allocation allowed)
// ---------------------------------------------------------------------------
struct Scratch {
    __nv_bfloat16 hidden[SEQ * HID];
    __nv_bfloat16 w[7][HID * HID];       // q,k,v,o,gate,up,down (bf16)
    __nv_bfloat16 q[SEQ * HID];
    __nv_bfloat16 k[SEQ * HID];
    __nv_bfloat16 v[SEQ * HID];
    __nv_bfloat16 scores[SEQ * AKEY];
    __nv_bfloat16 probs[SEQ * AKEY];
    __nv_bfloat16 ctx[SEQ * HID];
    __nv_bfloat16 post[SEQ * HID];
    __nv_bfloat16 gate[SEQ * HID];
    __nv_bfloat16 up[SEQ * HID];
    __nv_bfloat16 gated[SEQ * HID];
    float         f32buf[SEQ * HID];     // fp32 GEMM accumulator output
};
__device__ Scratch g_s;

// ---------------------------------------------------------------------------
// f32 -> bf16 conversion for hidden + 7 weights (one launch, gridDim.y = tensor)
// ---------------------------------------------------------------------------
struct CvtPack { const float* s[8]; __nv_bfloat16* d[8]; };

__global__ void cvt8_kernel(CvtPack p, int n4) {
    int t = blockIdx.y;
    const float4* src = reinterpret_cast<const float4*>(p.s[t]);
    __nv_bfloat162* dst = reinterpret_cast<__nv_bfloat162*>(p.d[t]);
    for (int i = blockIdx.x * blockDim.x + threadIdx.x; i < n4;
         i += gridDim.x * blockDim.x) {
        float4 v = src[i];
        dst[2 * i]     = __floats2bfloat162_rn(v.x, v.y);
        dst[2 * i + 1] = __floats2bfloat162_rn(v.z, v.w);
    }
}

// ---------------------------------------------------------------------------
// Generic bf16 GEMM, fp32 output: Cf[M,N] = A[M,K] * op(B)
//   BT=false : op(B) = B,   B row-major [K, N]
//   BT=true  : op(B) = B^T, B row-major [N, K]
// Block 128x128, K-tile 32, 8 warps (4 over M x 2 over N), warp tile 32x64.
// Register-prefetch, single smem buffer, direct f32 global store epilogue.
// ---------------------------------------------------------------------------
constexpr int BM = 128, BN = 128, BK = 32;

template <bool BT>
__global__ __launch_bounds__(256)
void gemm_bf16(const __nv_bfloat16* __restrict__ A,
               const __nv_bfloat16* __restrict__ B,
               float* __restrict__ Cf,
               int K, int lda, int ldb, int ldc) {
    constexpr int SA    = BK + 8;                    // 40 elems = 80B rows
    constexpr int BROWS = BT ? BN : BK;
    constexpr int BCOLS = BT ? BK + 8 : BN + 8;      // 40 / 136

    __shared__ __align__(16) __nv_bfloat16 As[BM][SA];
    __shared__ __align__(16) __nv_bfloat16 Bs[BROWS][BCOLS];

    const int tid = threadIdx.x;
    const int bm = blockIdx.y * BM;
    const int bn = blockIdx.x * BN;

    uint4 ra[2], rb[2];

    auto gload = [&](int t) {
        const int k0 = t * BK;
#pragma unroll
        for (int v = 0; v < 2; v++) {                // A tile: 512 x 16B vectors
            int vi = tid + v * 256;
            int ar = vi >> 2, ac = (vi & 3) * 8;
            ra[v] = *reinterpret_cast<const uint4*>(A + (size_t)(bm + ar) * lda + k0 + ac);
        }
        if constexpr (BT) {
#pragma unroll
            for (int v = 0; v < 2; v++) {            // B rows = N dim, k-contiguous
                int vi = tid + v * 256;
                int br = vi >> 2, bc = (vi & 3) * 8;
                rb[v] = *reinterpret_cast<const uint4*>(B + (size_t)(bn + br) * ldb + k0 + bc);
            }
        } else {
#pragma unroll
            for (int v = 0; v < 2; v++) {            // B rows = K dim, n-contiguous
                int vi = tid + v * 256;
                int br = vi >> 4, bc = (vi & 15) * 8;
                rb[v] = *reinterpret_cast<const uint4*>(B + (size_t)(k0 + br) * ldb + bn + bc);
            }
        }
    };

    auto sstore = [&]() {
#pragma unroll
        for (int v = 0; v < 2; v++) {
            int vi = tid + v * 256;
            int ar = vi >> 2, ac = (vi & 3) * 8;
            *reinterpret_cast<uint4*>(&As[ar][ac]) = ra[v];
        }
        if constexpr (BT) {
#pragma unroll
            for (int v = 0; v < 2; v++) {
                int vi = tid + v * 256;
                int br = vi >> 2, bc = (vi & 3) * 8;
                *reinterpret_cast<uint4*>(&Bs[br][bc]) = rb[v];
            }
        } else {
#pragma unroll
            for (int v = 0; v < 2; v++) {
                int vi = tid + v * 256;
                int br = vi >> 4, bc = (vi & 15) * 8;
                *reinterpret_cast<uint4*>(&Bs[br][bc]) = rb[v];
            }
        }
    };

    using BL = std::conditional_t<BT, wmma::col_major, wmma::row_major>;

    wmma::fragment<wmma::accumulator, 16, 16, 16, float> acc[2][4];
#pragma unroll
    for (int i = 0; i < 2; i++)
#pragma unroll
        for (int j = 0; j < 4; j++) wmma::fill_fragment(acc[i][j], 0.0f);

    const int wid = tid >> 5;
    const int wm = (wid & 3) * 32;     // warp M offset in block
    const int wn = (wid >> 2) * 64;    // warp N offset in block

    const int nt = K / BK;
    gload(0);

    for (int t = 0; t < nt; t++) {
        __syncthreads();               // prior-iter smem reads done
        sstore();
        __syncthreads();               // tile visible to all warps
        if (t + 1 < nt) gload(t + 1);  // overlap next global load with compute

#pragma unroll
        for (int kk = 0; kk < BK; kk += 16) {
            wmma::fragment<wmma::matrix_a, 16, 16, 16, __nv_bfloat16, wmma::row_major> af[2];
            wmma::fragment<wmma::matrix_b, 16, 16, 16, __nv_bfloat16, BL> bfr[4];
#pragma unroll
            for (int i = 0; i < 2; i++)
                wmma::load_matrix_sync(af[i], &As[wm + i * 16][kk], SA);
#pragma unroll
            for (int j = 0; j < 4; j++) {
                if constexpr (BT)
                    wmma::load_matrix_sync(bfr[j], &Bs[wn + j * 16][kk], BCOLS);
                else
                    wmma::load_matrix_sync(bfr[j], &Bs[kk][wn + j * 16], BCOLS);
            }
#pragma unroll
            for (int i = 0; i < 2; i++)
#pragma unroll
                for (int j = 0; j < 4; j++)
                    wmma::mma_sync(acc[i][j], af[i], bfr[j], acc[i][j]);
        }
    }

    // Epilogue: store fp32 fragments straight to global scratch
#pragma unroll
    for (int i = 0; i < 2; i++)
#pragma unroll
        for (int j = 0; j < 4; j++) {
            float* dst = Cf + (size_t)(bm + wm + i * 16) * ldc + (bn + wn + j * 16);
            wmma::store_matrix_sync(dst, acc[i][j], ldc, wmma::mem_row_major);
        }
}

// ---------------------------------------------------------------------------
// Elementwise converts (match reference rounding points)
// ---------------------------------------------------------------------------
__global__ void cvt_kernel(const float* __restrict__ s,
                           __nv_bfloat16* __restrict__ d, int n2) {
    for (int i = blockIdx.x * blockDim.x + threadIdx.x; i < n2;
         i += gridDim.x * blockDim.x) {
        float2 v = reinterpret_cast<const float2*>(s)[i];
        reinterpret_cast<__nv_bfloat162*>(d)[i] = __floats2bfloat162_rn(v.x, v.y);
    }
}

// d = bf16( f32(res) + f32(bf16(s)) )   (bf16 destination, internal residual)
__global__ void cvt_res_kernel(const float* __restrict__ s,
                               const __nv_bfloat16* __restrict__ res,
                               __nv_bfloat16* __restrict__ d, int n2) {
    for (int i = blockIdx.x * blockDim.x + threadIdx.x; i < n2;
         i += gridDim.x * blockDim.x) {
        float2 v = reinterpret_cast<const float2*>(s)[i];
        __nv_bfloat162 t = __floats2bfloat162_rn(v.x, v.y);
        __nv_bfloat162 r = reinterpret_cast<const __nv_bfloat162*>(res)[i];
        float ox = __bfloat162float(r.x) + __bfloat162float(t.x);
        float oy = __bfloat162float(r.y) + __bfloat162float(t.y);
        reinterpret_cast<__nv_bfloat162*>(d)[i] = __floats2bfloat162_rn(ox, oy);
    }
}

// FINAL output: d_out is float32 (f32 upcast of the reference's bf16 return):
//   out = f32( bf16( f32(res) + f32(bf16(s)) ) )
__global__ void cvt_res_f32_kernel(const float* __restrict__ s,
                                   const __nv_bfloat16* __restrict__ res,
                                   float* __restrict__ d, int n2) {
    for (int i = blockIdx.x * blockDim.x + threadIdx.x; i < n2;
         i += gridDim.x * blockDim.x) {
        float2 v = reinterpret_cast<const float2*>(s)[i];
        __nv_bfloat162 t = __floats2bfloat162_rn(v.x, v.y);
        __nv_bfloat162 r = reinterpret_cast<const __nv_bfloat162*>(res)[i];
        float ox = __bfloat162float(r.x) + __bfloat162float(t.x);
        float oy = __bfloat162float(r.y) + __bfloat162float(t.y);
        __nv_bfloat162 ob = __floats2bfloat162_rn(ox, oy);
        float2 o;
        o.x = __bfloat162float(ob.x);
        o.y = __bfloat162float(ob.y);
        reinterpret_cast<float2*>(d)[i] = o;
    }
}

// ---------------------------------------------------------------------------
// Softmax over rows of scores[SEQ, AKEY]; reference rounding:
//   bf16 scores -> f32 * (1/sqrt(H)) -> bf16 -> f32 softmax -> bf16
// ---------------------------------------------------------------------------
__global__ void softmax_kernel(const __nv_bfloat16* __restrict__ sc,
                               __nv_bfloat16* __restrict__ pr) {
    const int row = blockIdx.x;
    const int tid = threadIdx.x;
    const float scale = 0.022097086912079608f;  // 1/sqrt(2048)
    __shared__ float sh[256];

    float x[4];
#pragma unroll
    for (int i = 0; i < 4; i++) {
        float vraw = __bfloat162float(sc[(size_t)row * AKEY + tid + i * 256]) * scale;
        x[i] = __bfloat162float(__float2bfloat16(vraw));
    }
    float m = fmaxf(fmaxf(x[0], x[1]), fmaxf(x[2], x[3]));
    sh[tid] = m; __syncthreads();
    for (int s = 128; s > 0; s >>= 1) {
        if (tid < s) sh[tid] = fmaxf(sh[tid], sh[tid + s]);
        __syncthreads();
    }
    m = sh[0]; __syncthreads();

    float e[4]; float sum = 0.f;
#pragma unroll
    for (int i = 0; i < 4; i++) { e[i] = expf(x[i] - m); sum += e[i]; }
    sh[tid] = sum; __syncthreads();
    for (int s = 128; s > 0; s >>= 1) {
        if (tid < s) sh[tid] += sh[tid + s];
        __syncthreads();
    }
    const float tot = sh[0];
#pragma unroll
    for (int i = 0; i < 4; i++)
        pr[(size_t)row * AKEY + tid + i * 256] = __float2bfloat16(e[i] / tot);
}

// ---------------------------------------------------------------------------
// gated = bf16( f32(bf16(gelu_tanh(f32(gate)))) * f32(up) )
// ---------------------------------------------------------------------------
__global__ void gelu_mul_kernel(const __nv_bfloat16* __restrict__ g,
                                const __nv_bfloat16* __restrict__ u,
                                __nv_bfloat16* __restrict__ o, int n) {
    for (int i = blockIdx.x * blockDim.x + threadIdx.x; i < n;
         i += gridDim.x * blockDim.x) {
        float x = __bfloat162float(g[i]);
        float t = tanhf(0.7978845608028654f * (x + 0.044715f * x * x * x));
        float act = 0.5f * x * (1.0f + t);
        __nv_bfloat16 ab = __float2bfloat16(act);
        o[i] = __float2bfloat16(__bfloat162float(ab) * __bfloat162float(u[i]));
    }
}

// ---------------------------------------------------------------------------
// kernel_launch
// ---------------------------------------------------------------------------
extern "C" void kernel_launch(void* const* d_in, const int* in_sizes, int n_in,
                              void* d_out, int out_size) {
    Scratch* S;
    cudaGetSymbolAddress((void**)&S, g_s);

    // input order: hidden, q_proj, k_proj, v_proj, o_proj, gate_proj, up_proj, down_proj
    CvtPack p;
    p.s[0] = (const float*)d_in[0]; p.d[0] = S->hidden;
    for (int i = 1; i < 8; i++) { p.s[i] = (const float*)d_in[i]; p.d[i] = S->w[i - 1]; }
    cvt8_kernel<<<dim3(256, 8), 256>>>(p, SEQ * HID / 4);

    const dim3 blk(256);
    const dim3 gFull(HID / BN, SEQ / BM);   // (16,16)
    const dim3 gScor(AKEY / BN, SEQ / BM);  // (8,16)
    const int nFull2 = SEQ * HID / 2;
    const int nScor2 = SEQ * AKEY / 2;
    float* F = S->f32buf;

    // q, k, v projections
    gemm_bf16<false><<<gFull, blk>>>(S->hidden, S->w[0], F, HID, HID, HID, HID);
    cvt_kernel<<<2048, 256>>>(F, S->q, nFull2);
    gemm_bf16<false><<<gFull, blk>>>(S->hidden, S->w[1], F, HID, HID, HID, HID);
    cvt_kernel<<<2048, 256>>>(F, S->k, nFull2);
    gemm_bf16<false><<<gFull, blk>>>(S->hidden, S->w[2], F, HID, HID, HID, HID);
    cvt_kernel<<<2048, 256>>>(F, S->v, nFull2);

    // scores = q @ k[:AKEY]^T
    gemm_bf16<true><<<gScor, blk>>>(S->q, S->k, F, HID, HID, HID, AKEY);
    cvt_kernel<<<2048, 256>>>(F, S->scores, nScor2);

    // probs = softmax(scale * scores)
    softmax_kernel<<<SEQ, 256>>>(S->scores, S->probs);

    // context = probs @ v[:AKEY]
    gemm_bf16<false><<<gFull, blk>>>(S->probs, S->v, F, AKEY, AKEY, HID, HID);
    cvt_kernel<<<2048, 256>>>(F, S->ctx, nFull2);

    // post = bf16(f32(hidden_bf) + f32(bf16(ctx @ o_proj)))
    gemm_bf16<false><<<gFull, blk>>>(S->ctx, S->w[3], F, HID, HID, HID, HID);
    cvt_res_kernel<<<2048, 256>>>(F, S->hidden, S->post, nFull2);

    // gate / up projections
    gemm_bf16<false><<<gFull, blk>>>(S->post, S->w[4], F, HID, HID, HID, HID);
    cvt_kernel<<<2048, 256>>>(F, S->gate, nFull2);
    gemm_bf16<false><<<gFull, blk>>>(S->post, S->w[5], F, HID, HID, HID, HID);
    cvt_kernel<<<2048, 256>>>(F, S->up, nFull2);

    // gated = bf16(bf16(gelu(gate)) * up)
    gelu_mul_kernel<<<4096, 256>>>(S->gate, S->up, S->gated, SEQ * HID);

    // out(f32) = f32( bf16( f32(post) + f32(bf16(gated @ down_proj)) ) )
    gemm_bf16<false><<<gFull, blk>>>(S->gated, S->w[6], F, HID, HID, HID, HID);
    cvt_res_f32_kernel<<<2048, 256>>>(F, S->post, (float*)d_out, nFull2);
}

// round 8
// speedup vs baseline: 1.1259x; 1.1259x over previous
#include <cuda_runtime.h>
#include <cuda_bf16.h>
#include <mma.h>
#include <type_traits>

using namespace nvcuda;

#define SEQ  2048
#define HID  2048
#define AKEY 1024

// ---------------------------------------------------------------------------
// Scratch (device-global; no runtime allocation allowed)
// ---------------------------------------------------------------------------
struct Scratch {
    __nv_bfloat16 hidden[SEQ * HID];
    __nv_bfloat16 w[7][HID * HID];       // q,k,v,o,gate,up,down (bf16) — contiguous
    __nv_bfloat16 q[SEQ * HID];          // q,k,v contiguous for batched GEMM
    __nv_bfloat16 k[SEQ * HID];
    __nv_bfloat16 v[SEQ * HID];
    __nv_bfloat16 scores[SEQ * AKEY];
    __nv_bfloat16 probs[SEQ * AKEY];
    __nv_bfloat16 ctx[SEQ * HID];
    __nv_bfloat16 post[SEQ * HID];
    __nv_bfloat16 gate[SEQ * HID];       // gate,up contiguous for batched GEMM
    __nv_bfloat16 up[SEQ * HID];
    __nv_bfloat16 gated[SEQ * HID];
};
__device__ Scratch g_s;

// ---------------------------------------------------------------------------
// f32 -> bf16 conversion for hidden + 7 weights (one launch, gridDim.y = tensor)
// ---------------------------------------------------------------------------
struct CvtPack { const float* s[8]; __nv_bfloat16* d[8]; };

__global__ void cvt8_kernel(CvtPack p, int n4) {
    int t = blockIdx.y;
    const float4* src = reinterpret_cast<const float4*>(p.s[t]);
    __nv_bfloat162* dst = reinterpret_cast<__nv_bfloat162*>(p.d[t]);
    for (int i = blockIdx.x * blockDim.x + threadIdx.x; i < n4;
         i += gridDim.x * blockDim.x) {
        float4 v = src[i];
        dst[2 * i]     = __floats2bfloat162_rn(v.x, v.y);
        dst[2 * i + 1] = __floats2bfloat162_rn(v.z, v.w);
    }
}

// ---------------------------------------------------------------------------
// cp.async helpers
// ---------------------------------------------------------------------------
__device__ __forceinline__ void cp_async16(void* smem, const void* gmem) {
    unsigned sa = (unsigned)__cvta_generic_to_shared(smem);
    asm volatile("cp.async.cg.shared.global [%0], [%1], 16;\n" ::"r"(sa), "l"(gmem));
}
#define CP_COMMIT() asm volatile("cp.async.commit_group;\n" ::: "memory")
#define CP_WAIT0()  asm volatile("cp.async.wait_group 0;\n" ::: "memory")

// ---------------------------------------------------------------------------
// Generic bf16 GEMM with fused epilogue:  C = epi(A[M,K] * op(B))
//   BT=false : op(B) = B,   B row-major [K, N]
//   BT=true  : op(B) = B^T, B row-major [N, K]
//   EPI=0 : C(bf16) = bf16(acc)
//   EPI=1 : C(bf16) = bf16( f32(Res) + f32(bf16(acc)) )
//   EPI=2 : C(f32)  = f32( bf16( f32(Res) + f32(bf16(acc)) ) )   [final output]
// Batched over blockIdx.z: B += z*wstride, C += z*ostride (A, Res shared).
// Block 128x128, K-tile 32, 8 warps (4 M x 2 N), warp tile 32x64,
// cp.async double-buffered mainloop, smem-staged epilogue.
// ---------------------------------------------------------------------------
constexpr int BM = 128, BN = 128, BK = 32;

template <bool BT, int EPI>
__global__ __launch_bounds__(256)
void gemm_bf16(const __nv_bfloat16* __restrict__ A,
               const __nv_bfloat16* __restrict__ B,
               const __nv_bfloat16* __restrict__ Res,
               void* __restrict__ Cv,
               int K, int lda, int ldb, int ldc,
               size_t wstride, size_t ostride) {
    constexpr int SA    = BK + 8;                    // 40 elems = 80B rows
    constexpr int BROWS = BT ? BN : BK;
    constexpr int BCOLS = BT ? BK + 8 : BN + 8;      // 40 / 136
    constexpr int ABYTES = 2 * BM * SA * (int)sizeof(__nv_bfloat16);
    constexpr int BBYTES = 2 * BROWS * BCOLS * (int)sizeof(__nv_bfloat16);

    __shared__ __align__(16) char smem[ABYTES + BBYTES];
    typedef __nv_bfloat16 (*ATile)[BM][SA];
    typedef __nv_bfloat16 (*BTile)[BROWS][BCOLS];
    ATile As = reinterpret_cast<ATile>(smem);
    BTile Bs = reinterpret_cast<BTile>(smem + ABYTES);

    const int tid = threadIdx.x;
    const int bm = blockIdx.y * BM;
    const int bn = blockIdx.x * BN;

    B += (size_t)blockIdx.z * wstride;

    auto loadTile = [&](int t, int buf) {
        const int k0 = t * BK;
#pragma unroll
        for (int v = 0; v < 2; v++) {                // A: 512 x 16B vectors
            int vi = tid + v * 256;
            int ar = vi >> 2, ac = (vi & 3) * 8;
            cp_async16(&(*As)[buf * 0 + 0][0] + 0, nullptr); // (never taken; placate)
        }
    };
    // (lambda above unused; explicit loads below for clarity)

    auto load = [&](int t, int buf) {
        const int k0 = t * BK;
#pragma unroll
        for (int v = 0; v < 2; v++) {
            int vi = tid + v * 256;
            int ar = vi >> 2, ac = (vi & 3) * 8;
            cp_async16(&As[buf][ar][ac], A + (size_t)(bm + ar) * lda + k0 + ac);
        }
        if constexpr (BT) {
#pragma unroll
            for (int v = 0; v < 2; v++) {
                int vi = tid + v * 256;
                int br = vi >> 2, bc = (vi & 3) * 8;
                cp_async16(&Bs[buf][br][bc], B + (size_t)(bn + br) * ldb + k0 + bc);
            }
        } else {
#pragma unroll
            for (int v = 0; v < 2; v++) {
                int vi = tid + v * 256;
                int br = vi >> 4, bc = (vi & 15) * 8;
                cp_async16(&Bs[buf][br][bc], B + (size_t)(k0 + br) * ldb + bn + bc);
            }
        }
    };

    using BL = std::conditional_t<BT, wmma::col_major, wmma::row_major>;

    wmma::fragment<wmma::accumulator, 16, 16, 16, float> acc[2][4];
#pragma unroll
    for (int i = 0; i < 2; i++)
#pragma unroll
        for (int j = 0; j < 4; j++) wmma::fill_fragment(acc[i][j], 0.0f);

    const int wid  = tid >> 5;
    const int lane = tid & 31;
    const int wm = (wid & 3) * 32;
    const int wn = (wid >> 2) * 64;

    const int nt = K / BK;
    load(0, 0);
    CP_COMMIT();

    for (int t = 0; t < nt; t++) {
        CP_WAIT0();
        __syncthreads();
        if (t + 1 < nt) { load(t + 1, (t + 1) & 1); CP_COMMIT(); }
        const int buf = t & 1;
#pragma unroll
        for (int kk = 0; kk < BK; kk += 16) {
            wmma::fragment<wmma::matrix_a, 16, 16, 16, __nv_bfloat16, wmma::row_major> af[2];
            wmma::fragment<wmma::matrix_b, 16, 16, 16, __nv_bfloat16, BL> bfr[4];
#pragma unroll
            for (int i = 0; i < 2; i++)
                wmma::load_matrix_sync(af[i], &As[buf][wm + i * 16][kk], SA);
#pragma unroll
            for (int j = 0; j < 4; j++) {
                if constexpr (BT)
                    wmma::load_matrix_sync(bfr[j], &Bs[buf][wn + j * 16][kk], BCOLS);
                else
                    wmma::load_matrix_sync(bfr[j], &Bs[buf][kk][wn + j * 16], BCOLS);
            }
#pragma unroll
            for (int i = 0; i < 2; i++)
#pragma unroll
                for (int j = 0; j < 4; j++)
                    wmma::mma_sync(acc[i][j], af[i], bfr[j], acc[i][j]);
        }
        __syncthreads();
    }

    // -------- fused epilogue: per-warp 16x16 smem stage (aliases tile smem) --
    float (*stage)[20] = reinterpret_cast<float(*)[20]>(smem + wid * 16 * 20 * sizeof(float));
    const int r  = lane >> 1;
    const int c0 = (lane & 1) * 8;

    __nv_bfloat16* Cb = reinterpret_cast<__nv_bfloat16*>(Cv) + (size_t)blockIdx.z * ostride;
    float*         Cf = reinterpret_cast<float*>(Cv);

#pragma unroll
    for (int i = 0; i < 2; i++) {
#pragma unroll
        for (int j = 0; j < 4; j++) {
            wmma::store_matrix_sync(&stage[0][0], acc[i][j], 20, wmma::mem_row_major);
            __syncwarp();
            const int grow = bm + wm + i * 16 + r;
            const int gcol = bn + wn + j * 16 + c0;
            const size_t base = (size_t)grow * ldc + gcol;

            if constexpr (EPI == 0) {
                __nv_bfloat162 ob[4];
#pragma unroll
                for (int c = 0; c < 4; c++)
                    ob[c] = __floats2bfloat162_rn(stage[r][c0 + 2 * c],
                                                  stage[r][c0 + 2 * c + 1]);
                *reinterpret_cast<uint4*>(Cb + base) = *reinterpret_cast<uint4*>(ob);
            } else {
                uint4 rv4 = *reinterpret_cast<const uint4*>(Res + base);
                const __nv_bfloat162* rp = reinterpret_cast<const __nv_bfloat162*>(&rv4);
                if constexpr (EPI == 1) {
                    __nv_bfloat162 ob[4];
#pragma unroll
                    for (int c = 0; c < 4; c++) {
                        __nv_bfloat162 t2 = __floats2bfloat162_rn(stage[r][c0 + 2 * c],
                                                                  stage[r][c0 + 2 * c + 1]);
                        float ox = __bfloat162float(rp[c].x) + __bfloat162float(t2.x);
                        float oy = __bfloat162float(rp[c].y) + __bfloat162float(t2.y);
                        ob[c] = __floats2bfloat162_rn(ox, oy);
                    }
                    *reinterpret_cast<uint4*>(Cb + base) = *reinterpret_cast<uint4*>(ob);
                } else {  // EPI == 2 : f32 final output
                    float of[8];
#pragma unroll
                    for (int c = 0; c < 4; c++) {
                        __nv_bfloat162 t2 = __floats2bfloat162_rn(stage[r][c0 + 2 * c],
                                                                  stage[r][c0 + 2 * c + 1]);
                        float ox = __bfloat162float(rp[c].x) + __bfloat162float(t2.x);
                        float oy = __bfloat162float(rp[c].y) + __bfloat162float(t2.y);
                        __nv_bfloat162 ob2 = __floats2bfloat162_rn(ox, oy);
                        of[2 * c]     = __bfloat162float(ob2.x);
                        of[2 * c + 1] = __bfloat162float(ob2.y);
                    }
                    *reinterpret_cast<float4*>(Cf + base)     = *reinterpret_cast<float4*>(of);
                    *reinterpret_cast<float4*>(Cf + base + 4) = *reinterpret_cast<float4*>(of + 4);
                }
            }
            __syncwarp();
        }
    }
}

// ---------------------------------------------------------------------------
// Softmax over rows of scores[SEQ, AKEY]; reference rounding:
//   bf16 scores -> f32 * (1/sqrt(H)) -> bf16 -> f32 softmax -> bf16
// ---------------------------------------------------------------------------
__global__ void softmax_kernel(const __nv_bfloat16* __restrict__ sc,
                               __nv_bfloat16* __restrict__ pr) {
    const int row = blockIdx.x;
    const int tid = threadIdx.x;
    const float scale = 0.022097086912079608f;  // 1/sqrt(2048)
    __shared__ float sh[256];

    float x[4];
#pragma unroll
    for (int i = 0; i < 4; i++) {
        float vraw = __bfloat162float(sc[(size_t)row * AKEY + tid + i * 256]) * scale;
        x[i] = __bfloat162float(__float2bfloat16(vraw));
    }
    float m = fmaxf(fmaxf(x[0], x[1]), fmaxf(x[2], x[3]));
    sh[tid] = m; __syncthreads();
    for (int s = 128; s > 0; s >>= 1) {
        if (tid < s) sh[tid] = fmaxf(sh[tid], sh[tid + s]);
        __syncthreads();
    }
    m = sh[0]; __syncthreads();

    float e[4]; float sum = 0.f;
#pragma unroll
    for (int i = 0; i < 4; i++) { e[i] = expf(x[i] - m); sum += e[i]; }
    sh[tid] = sum; __syncthreads();
    for (int s = 128; s > 0; s >>= 1) {
        if (tid < s) sh[tid] += sh[tid + s];
        __syncthreads();
    }
    const float tot = sh[0];
#pragma unroll
    for (int i = 0; i < 4; i++)
        pr[(size_t)row * AKEY + tid + i * 256] = __float2bfloat16(e[i] / tot);
}

// ---------------------------------------------------------------------------
// gated = bf16( f32(bf16(gelu_tanh(f32(gate)))) * f32(up) )
// ---------------------------------------------------------------------------
__global__ void gelu_mul_kernel(const __nv_bfloat16* __restrict__ g,
                                const __nv_bfloat16* __restrict__ u,
                                __nv_bfloat16* __restrict__ o, int n2) {
    for (int i = blockIdx.x * blockDim.x + threadIdx.x; i < n2;
         i += gridDim.x * blockDim.x) {
        __nv_bfloat162 gv = reinterpret_cast<const __nv_bfloat162*>(g)[i];
        __nv_bfloat162 uv = reinterpret_cast<const __nv_bfloat162*>(u)[i];
        float xs[2] = {__bfloat162float(gv.x), __bfloat162float(gv.y)};
        float us[2] = {__bfloat162float(uv.x), __bfloat162float(uv.y)};
        float os[2];
#pragma unroll
        for (int c = 0; c < 2; c++) {
            float x = xs[c];
            float t = tanhf(0.7978845608028654f * (x + 0.044715f * x * x * x));
            float act = 0.5f * x * (1.0f + t);
            float ab = __bfloat162float(__float2bfloat16(act));
            os[c] = ab * us[c];
        }
        reinterpret_cast<__nv_bfloat162*>(o)[i] = __floats2bfloat162_rn(os[0], os[1]);
    }
}

// ---------------------------------------------------------------------------
// kernel_launch
// ---------------------------------------------------------------------------
extern "C" void kernel_launch(void* const* d_in, const int* in_sizes, int n_in,
                              void* d_out, int out_size) {
    Scratch* S;
    cudaGetSymbolAddress((void**)&S, g_s);

    // input order: hidden, q_proj, k_proj, v_proj, o_proj, gate_proj, up_proj, down_proj
    CvtPack p;
    p.s[0] = (const float*)d_in[0]; p.d[0] = S->hidden;
    for (int i = 1; i < 8; i++) { p.s[i] = (const float*)d_in[i]; p.d[i] = S->w[i - 1]; }
    cvt8_kernel<<<dim3(256, 8), 256>>>(p, SEQ * HID / 4);

    const dim3 blk(256);
    const size_t WS = (size_t)HID * HID;   // weight stride
    const size_t OS = (size_t)SEQ * HID;   // output stride

    // q,k,v = hidden @ {wq,wk,wv}   (batched over z)
    gemm_bf16<false, 0><<<dim3(16, 16, 3), blk>>>(
        S->hidden, S->w[0], nullptr, S->q, HID, HID, HID, HID, WS, OS);

    // scores = q @ k[:AKEY]^T
    gemm_bf16<true, 0><<<dim3(8, 16, 1), blk>>>(
        S->q, S->k, nullptr, S->scores, HID, HID, HID, AKEY, 0, 0);

    // probs = softmax(scale * scores)
    softmax_kernel<<<SEQ, 256>>>(S->scores, S->probs);

    // context = probs @ v[:AKEY]
    gemm_bf16<false, 0><<<dim3(16, 16, 1), blk>>>(
        S->probs, S->v, nullptr, S->ctx, AKEY, AKEY, HID, HID, 0, 0);

    // post = bf16(f32(hidden_bf) + f32(bf16(ctx @ o_proj)))
    gemm_bf16<false, 1><<<dim3(16, 16, 1), blk>>>(
        S->ctx, S->w[3], S->hidden, S->post, HID, HID, HID, HID, 0, 0);

    // gate,up = post @ {w_gate, w_up}  (batched over z)
    gemm_bf16<false, 0><<<dim3(16, 16, 2), blk>>>(
        S->post, S->w[4], nullptr, S->gate, HID, HID, HID, HID, WS, OS);

    // gated = bf16(bf16(gelu(gate)) * up)
    gelu_mul_kernel<<<2048, 256>>>(S->gate, S->up, S->gated, SEQ * HID / 2);

    // out(f32) = f32( bf16( f32(post) + f32(bf16(gated @ down_proj)) ) )
    gemm_bf16<false, 2><<<dim3(16, 16, 1), blk>>>(
        S->gated, S->w[6], S->post, d_out, HID, HID, HID, HID, 0, 0);
}